// round 10
// baseline (speedup 1.0000x reference)
#include <cuda_runtime.h>
#include <cuda_fp16.h>

#define BB   256
#define TT   2048
#define QD   1024
#define AD   128
#define DCH  8
#define DKK  21
#define PLL  11
#define MHS  24        // half2 per M row: taps 0..20, [21]=(tb,tb), [22..23]=0
#define SALN 2080      // per-batch padded alignment (10 left pad + tail zeros)
#define NTHR 1024      // 2 batches x 512 threads x 4 positions

// dynamic smem layout (floats):
//   mh  : 2*3072   (half2[2][128*24])      offset 0
//   sal : 2*2080                            offset 6144
//   shq : 2*1024                            offset 10304
//   shh : 2*128                             offset 12352
//   shG : 2*168                             offset 12608
//   sv  : 2*128                             offset 12944
//   sp  : 16                                offset 13200
//   red : 2*16                              offset 13216
#define SMEM_FLOATS 13248

__device__ __forceinline__ float warp_sum(float v) {
#pragma unroll
    for (int o = 16; o; o >>= 1) v += __shfl_xor_sync(~0u, v, o);
    return v;
}

__device__ __forceinline__ __half2 tanh2(__half2 x) {
    unsigned xi = *reinterpret_cast<unsigned*>(&x), yi;
    asm("tanh.approx.f16x2 %0, %1;" : "=r"(yi) : "r"(xi));
    return *reinterpret_cast<__half2*>(&yi);
}

__global__ __launch_bounds__(NTHR, 1) void dca_fused_kernel(
    const float* __restrict__ query,     const float* __restrict__ alignment,
    const float* __restrict__ P,         const float* __restrict__ W_w,
    const float* __restrict__ W_b,       const float* __restrict__ V_w,
    const float* __restrict__ F_w,       const float* __restrict__ U_w,
    const float* __restrict__ T_w,       const float* __restrict__ T_b,
    const float* __restrict__ v_w,       float* __restrict__ out)
{
    extern __shared__ float sdyn[];
    __half2* mh = (__half2*)sdyn;            // [2][AD*MHS]
    float* sal  = sdyn + 6144;               // [2][SALN]
    float* shq  = sdyn + 10304;              // [2][QD]
    float* shh  = sdyn + 12352;              // [2][AD]
    float* shG  = sdyn + 12608;              // [2][DCH*DKK]
    float* sv   = sdyn + 12944;              // [2][AD]
    float* sp   = sdyn + 13200;              // [PLL]
    float* red  = sdyn + 13216;              // [2][16]

    const int b0 = blockIdx.x * 2, tid = threadIdx.x;
    const int lane = tid & 31, wrp = tid >> 5;   // 32 warps

    // ---- loads: 2 queries, 2 alignment rows (contiguous), prior taps ----
    for (int i = tid; i < 2 * QD; i += NTHR) shq[i] = query[b0 * QD + i];
    for (int i = tid; i < 2 * TT; i += NTHR) {
        const int bb = i >> 11, t = i & (TT - 1);
        sal[bb * SALN + 10 + t] = alignment[b0 * TT + i];
    }
    if (tid < 10)  { sal[tid] = 0.f; sal[SALN + tid] = 0.f; }
    if (tid < 22)  { sal[2058 + tid] = 0.f; sal[SALN + 2058 + tid] = 0.f; }
    if (tid < PLL) sp[tid] = P[tid];
    __syncthreads();

    // ---- phase A1: h[bb][a] = tanh(dot(q_bb, W_w[a,:]) + W_b[a]) ----
    // 32 warps x 4 a-rows each; each W row read once, used for both batches.
#pragma unroll 1
    for (int i = 0; i < 4; i++) {
        const int a = wrp * 4 + i;
        const float4* wr = (const float4*)(W_w + a * QD);
        float d0 = 0.f, d1 = 0.f;
#pragma unroll
        for (int j = 0; j < 8; j++) {
            const float4 wv = wr[lane + 32 * j];
            const float4 q0 = *(const float4*)&shq[4 * lane + 128 * j];
            const float4 q1 = *(const float4*)&shq[QD + 4 * lane + 128 * j];
            d0 += wv.x * q0.x + wv.y * q0.y + wv.z * q0.z + wv.w * q0.w;
            d1 += wv.x * q1.x + wv.y * q1.y + wv.z * q1.z + wv.w * q1.w;
        }
        d0 = warp_sum(d0);
        d1 = warp_sum(d1);
        if (lane == 0) {
            const float wb = W_b[a];
            shh[a]      = tanhf(d0 + wb);
            shh[AD + a] = tanhf(d1 + wb);
        }
    }
    __syncthreads();

    // ---- phase A2: G[bb][r] = dot(h_bb, V_w[r,:]) ----
    for (int i = tid; i < 2 * DCH * DKK; i += NTHR) {
        const int bb = i / (DCH * DKK), r = i - bb * (DCH * DKK);
        const float4* vr = (const float4*)(V_w + r * AD);
        const float4* hr = (const float4*)(shh + bb * AD);
        float acc = 0.f;
#pragma unroll
        for (int j = 0; j < AD / 4; j++) {
            const float4 vv = vr[j], hv = hr[j];
            acc += vv.x * hv.x + vv.y * hv.y + vv.z * hv.z + vv.w * hv.w;
        }
        shG[bb * DCH * DKK + r] = acc;
    }
    __syncthreads();

    // ---- phase A3: M[bb][a,k] -> duplicated half2; plus tb, v ----
    for (int i = tid; i < 2 * AD * DKK; i += NTHR) {
        const int bb = i / (AD * DKK);
        const int rem = i - bb * (AD * DKK);
        const int a = rem / DKK, k = rem - a * DKK;
        float m = 0.f;
#pragma unroll
        for (int c = 0; c < DCH; c++)
            m += U_w[a * DCH + c] * F_w[c * DKK + k]
               + T_w[a * DCH + c] * shG[bb * DCH * DKK + c * DKK + k];
        const __half hm = __float2half_rn(m);
        mh[bb * AD * MHS + a * MHS + k] = __halves2half2(hm, hm);
    }
    for (int i = tid; i < 2 * AD; i += NTHR) {
        const int bb = i >> 7, a = i & (AD - 1);
        __half2* row = mh + bb * AD * MHS + a * MHS;
        const __half htb = __float2half_rn(T_b[a]);
        row[21] = __halves2half2(htb, htb);
        row[22] = __halves2half2(__half(0.f), __half(0.f));
        row[23] = __halves2half2(__half(0.f), __half(0.f));
        sv[bb * AD + a] = v_w[a];
    }
    __syncthreads();

    // ---- phase B: conv via HFMA2, 4 positions/thread, 2 chains ----
    const int bb = tid >> 9, lt = tid & 511;
    const int t0 = lt * 4;                       // padded start index
    const float*   salb = sal + bb * SALN;
    const __half2* mhb  = mh  + bb * AD * MHS;
    const float*   svb  = sv  + bb * AD;

    float w[24];
#pragma unroll
    for (int k = 0; k < 24; k++) w[k] = salb[t0 + k];

    // prior first (exact fp32), so w[] can die after u[] is built
    float e0, e1, e2, e3;
    {
        float s0 = 0.f, s1 = 0.f, s2 = 0.f, s3 = 0.f;
#pragma unroll
        for (int k = 0; k < PLL; k++) {
            const float pk = sp[k];
            s0 += pk * w[k];     s1 += pk * w[k + 1];
            s2 += pk * w[k + 2]; s3 += pk * w[k + 3];
        }
        e0 = __logf(fmaxf(s0, 1e-6f));
        e1 = __logf(fmaxf(s1, 1e-6f));
        e2 = __logf(fmaxf(s2, 1e-6f));
        e3 = __logf(fmaxf(s3, 1e-6f));
    }

    __half2 u[23];
#pragma unroll
    for (int k = 0; k < 23; k++) u[k] = __floats2half2_rn(w[k], w[k + 1]);

#pragma unroll 1
    for (int a = 0; a < AD; a++) {
        const __half2* row = mhb + a * MHS;
        const uint4 q5 = *(const uint4*)(row + 20);   // tap20, (tb,tb), 0, 0
        const __half2 tap20 = ((const __half2*)&q5)[0];
        const __half2 tbtb  = ((const __half2*)&q5)[1];
        __half2 acc01 = tbtb, acc23 = tbtb;
#pragma unroll
        for (int c = 0; c < 5; c++) {
            const uint4 qc = *(const uint4*)(row + 4 * c);
            const __half2* t4 = (const __half2*)&qc;
#pragma unroll
            for (int i = 0; i < 4; i++) {
                const int k = 4 * c + i;
                acc01 = __hfma2(t4[i], u[k],     acc01);
                acc23 = __hfma2(t4[i], u[k + 2], acc23);
            }
        }
        acc01 = __hfma2(tap20, u[20], acc01);
        acc23 = __hfma2(tap20, u[22], acc23);

        const float2 f01 = __half22float2(tanh2(acc01));
        const float2 f23 = __half22float2(tanh2(acc23));
        const float v = svb[a];
        e0 += v * f01.x; e1 += v * f01.y;
        e2 += v * f23.x; e3 += v * f23.y;
    }

    // ---- softmax over T within each 512-thread half-block ----
    const int hwrp = wrp & 15;
    float* redb = red + bb * 16;

    float mx = fmaxf(fmaxf(e0, e1), fmaxf(e2, e3));
#pragma unroll
    for (int o = 16; o; o >>= 1) mx = fmaxf(mx, __shfl_xor_sync(~0u, mx, o));
    if (lane == 0) redb[hwrp] = mx;
    __syncthreads();
    mx = redb[0];
#pragma unroll
    for (int i = 1; i < 16; i++) mx = fmaxf(mx, redb[i]);
    __syncthreads();

    const float x0 = __expf(e0 - mx), x1 = __expf(e1 - mx);
    const float x2 = __expf(e2 - mx), x3 = __expf(e3 - mx);
    float sm = (x0 + x1) + (x2 + x3);
#pragma unroll
    for (int o = 16; o; o >>= 1) sm += __shfl_xor_sync(~0u, sm, o);
    if (lane == 0) redb[hwrp] = sm;
    __syncthreads();
    sm = redb[0];
#pragma unroll
    for (int i = 1; i < 16; i++) sm += redb[i];

    const float inv = 1.0f / sm;
    float4* o4 = (float4*)(out + (b0 + bb) * TT + t0);
    *o4 = make_float4(x0 * inv, x1 * inv, x2 * inv, x3 * inv);
}

extern "C" void kernel_launch(void* const* d_in, const int* in_sizes, int n_in,
                              void* d_out, int out_size)
{
    const float* query     = (const float*)d_in[0];
    const float* alignment = (const float*)d_in[1];
    const float* P         = (const float*)d_in[2];
    const float* W_w       = (const float*)d_in[3];
    const float* W_b       = (const float*)d_in[4];
    const float* V_w       = (const float*)d_in[5];
    const float* F_w       = (const float*)d_in[6];
    const float* U_w       = (const float*)d_in[7];
    const float* T_w       = (const float*)d_in[8];
    const float* T_b       = (const float*)d_in[9];
    const float* v_w       = (const float*)d_in[10];
    float* out = (float*)d_out;

    const int smem_bytes = SMEM_FLOATS * 4;
    cudaFuncSetAttribute(dca_fused_kernel,
                         cudaFuncAttributeMaxDynamicSharedMemorySize, smem_bytes);
    dca_fused_kernel<<<BB / 2, NTHR, smem_bytes>>>(
        query, alignment, P, W_w, W_b, V_w, F_w, U_w, T_w, T_b, v_w, out);
}